// round 5
// baseline (speedup 1.0000x reference)
#include <cuda_runtime.h>
#include <stdint.h>

#define NCOL   4096
#define TPB    256
#define KSEL   64
#define TGUESS 1.7f        // prefilter guess; exact fallback if it fails
#define CAP    2048        // candidate capacity (expected ~183 per row)

// float -> order-preserving uint32 (larger float => larger unsigned key)
__device__ __forceinline__ uint32_t f2k(float f) {
    uint32_t u = __float_as_uint(f);
    return u ^ (uint32_t)((((int32_t)u) >> 31) | (int32_t)0x80000000);
}
__device__ __forceinline__ float k2f(uint32_t k) {
    uint32_t u = (k & 0x80000000u) ? (k ^ 0x80000000u) : ~k;
    return __uint_as_float(u);
}

// inclusive block scan over TPB=256 uint32 values (fallback path only). wsum: shared[8].
__device__ __forceinline__ uint32_t block_scan_inc(uint32_t val, uint32_t* wsum, int t) {
    __syncthreads();
    int lane = t & 31, w = t >> 5;
#pragma unroll
    for (int off = 1; off < 32; off <<= 1) {
        uint32_t n = __shfl_up_sync(0xffffffffu, val, off);
        if (lane >= off) val += n;
    }
    if (lane == 31) wsum[w] = val;
    __syncthreads();
    if (w == 0) {
        uint32_t s = (lane < 8) ? wsum[lane] : 0u;
#pragma unroll
        for (int off = 1; off < 8; off <<= 1) {
            uint32_t n = __shfl_up_sync(0xffffffffu, s, off);
            if (lane >= off) s += n;
        }
        if (lane < 8) wsum[lane] = s;
    }
    __syncthreads();
    uint32_t base = (w > 0) ? wsum[w - 1] : 0u;
    return val + base;
}

__global__ __launch_bounds__(TPB, 8) void topk_mask_kernel(const float* __restrict__ x,
                                                           float* __restrict__ out) {
    __shared__ uint32_t cand[CAP];            // candidate keys; aliased as u16 tiebuf on tie path
    __shared__ uint32_t hist[256];
    __shared__ uint32_t wsum[8];
    __shared__ uint32_t s_pos, s_bin, s_above, s_h;
    __shared__ uint32_t s_keyT, s_need, s_eqc;
    __shared__ uint32_t keep_bm[NCOL / 32];

    const int t    = threadIdx.x;
    const int lane = t & 31;
    const size_t row_off = (size_t)blockIdx.x * NCOL;
    const float4* __restrict__ xr = (const float4*)(x + row_off);
    float4* __restrict__ outr     = (float4*)(out + row_off);

    if (t == 0) s_pos = 0;
    __syncthreads();

    // ---- phase 1: load + prefilter + warp-aggregated candidate compaction ----
#pragma unroll
    for (int h = 0; h < 2; h++) {
        float4 a = xr[(2 * h + 0) * TPB + t];
        float4 b = xr[(2 * h + 1) * TPB + t];
        float vals[8] = {a.x, a.y, a.z, a.w, b.x, b.y, b.z, b.w};
#pragma unroll
        for (int j = 0; j < 8; j++) {
            float fv = vals[j];
            bool pred = (fv > TGUESS);
            unsigned bal = __ballot_sync(0xffffffffu, pred);
            if (bal) {
                int leader = __ffs(bal) - 1;
                uint32_t base = 0;
                if (lane == leader) base = atomicAdd(&s_pos, (uint32_t)__popc(bal));
                base = __shfl_sync(0xffffffffu, base, leader);
                if (pred) {
                    uint32_t p = base + (uint32_t)__popc(bal & ((1u << lane) - 1u));
                    if (p < CAP) cand[p] = f2k(fv);
                }
            }
        }
    }
    __syncthreads();
    const uint32_t C = s_pos;
    const bool fast = (C >= KSEL && C <= CAP);

    // ---- phase 2: exact radix select for the K-th largest key ----
    if (fast) {
        if (t < 32) {   // warp 0 only
            uint32_t prefix = 0, mmask = 0, kth = KSEL;
#pragma unroll
            for (int pass = 0; pass < 4; pass++) {
                const int shift = 24 - 8 * pass;
#pragma unroll
                for (int j = 0; j < 8; j++) hist[lane * 8 + j] = 0;
                __syncwarp();
                for (uint32_t i = lane; i < C; i += 32) {
                    uint32_t kk = cand[i];
                    if ((kk & mmask) == prefix)
                        atomicAdd(&hist[(kk >> shift) & 0xFFu], 1u);
                }
                __syncwarp();
                // lane owns bins 255-8*lane .. 248-8*lane (descending); suffix sums
                uint32_t run = 0;
#pragma unroll
                for (int j = 0; j < 8; j++) run += hist[255 - lane * 8 - j];
                uint32_t excl = run;
#pragma unroll
                for (int off = 1; off < 32; off <<= 1) {
                    uint32_t n = __shfl_up_sync(0xffffffffu, excl, off);
                    if (lane >= off) excl += n;
                }
                excl -= run;                     // count in all bins above this lane's range
                uint32_t S = excl;
#pragma unroll
                for (int j = 0; j < 8; j++) {
                    uint32_t bin = 255u - (uint32_t)(lane * 8 + j);
                    uint32_t hh = hist[bin];
                    S += hh;
                    if (S >= kth && (S - hh) < kth) {   // unique boundary bin
                        s_bin = bin; s_above = S - hh; s_h = hh;
                    }
                }
                __syncwarp();
                prefix |= (s_bin << shift);
                mmask  |= (0xFFu << shift);
                kth    -= s_above;
                __syncwarp();
            }
            if (lane == 0) { s_keyT = prefix; s_need = kth; s_eqc = s_h; }
        }
        __syncthreads();
    } else {
        // fallback: exact block-wide radix over the whole row from L2 (never expected)
        uint32_t prefix = 0, mmask = 0, kth = KSEL;
#pragma unroll 1
        for (int pass = 0; pass < 4; pass++) {
            const int shift = 24 - 8 * pass;
            hist[t] = 0;
            __syncthreads();
            for (int i = t; i < NCOL; i += TPB) {
                uint32_t kk = f2k(x[row_off + i]);
                if ((kk & mmask) == prefix) {
                    uint32_t bin = (kk >> shift) & 0xFFu;
                    unsigned act = __activemask();
                    unsigned grp = __match_any_sync(act, bin);
                    if ((grp & ((1u << lane) - 1u)) == 0u)
                        atomicAdd(&hist[bin], (uint32_t)__popc(grp));
                }
            }
            __syncthreads();
            uint32_t hh = hist[255 - t];
            uint32_t S = block_scan_inc(hh, wsum, t);
            if (S >= kth && (S - hh) < kth) {
                s_bin = (uint32_t)(255 - t); s_above = S - hh; s_h = hh;
            }
            __syncthreads();
            prefix |= (s_bin << shift);
            mmask  |= (0xFFu << shift);
            kth    -= s_above;
            __syncthreads();
        }
        if (t == 0) { s_keyT = prefix; s_need = kth; s_eqc = s_h; }
        __syncthreads();
    }

    const uint32_t need = s_need;              // how many == T to keep (lowest cols first)
    const float Tf = k2f(s_keyT);              // exact K-th largest value
    const bool tie_rank = (s_eqc > need);      // rare: rank ties by column

    if (tie_rank) {
        uint16_t* tiebuf = (uint16_t*)cand;    // 4096 u16 fits in CAP u32 bytes
        if (t == 0) s_pos = 0;
        for (int i = t; i < NCOL / 32; i += TPB) keep_bm[i] = 0;
        __syncthreads();
        for (int i = t; i < NCOL; i += TPB) {
            if (x[row_off + i] == Tf) {
                uint32_t p = atomicAdd(&s_pos, 1u);
                tiebuf[p] = (uint16_t)i;
            }
        }
        __syncthreads();
        uint32_t total = s_pos;
        for (uint32_t i = t; i < total; i += TPB) {
            uint32_t ci = tiebuf[i], r = 0;
            for (uint32_t j = 0; j < total; j++) r += (tiebuf[j] < ci) ? 1u : 0u;
            if (r < need) atomicOr(&keep_bm[ci >> 5], 1u << (ci & 31));
        }
        __syncthreads();
        // tie-aware output
#pragma unroll
        for (int v = 0; v < 4; v++) {
            float4 q = xr[v * TPB + t];
            float4 o;
            float* ip = (float*)&q;
            float* op = (float*)&o;
#pragma unroll
            for (int j = 0; j < 4; j++) {
                float fv = ip[j];
                float val = 0.0f;
                if (fv > Tf) val = fv;
                else if (fv == Tf) {
                    uint32_t col = (uint32_t)(v * TPB + t) * 4u + (uint32_t)j;
                    if ((keep_bm[col >> 5] >> (col & 31)) & 1u) val = fv;
                }
                op[j] = val;
            }
            outr[v * TPB + t] = o;
        }
        return;
    }

    // ---- phase 3 (common): re-read row (L2-resident), 1 compare + 1 select per elem ----
#pragma unroll
    for (int v = 0; v < 4; v++) {
        float4 q = xr[v * TPB + t];
        float4 o;
        o.x = (q.x >= Tf) ? q.x : 0.0f;
        o.y = (q.y >= Tf) ? q.y : 0.0f;
        o.z = (q.z >= Tf) ? q.z : 0.0f;
        o.w = (q.w >= Tf) ? q.w : 0.0f;
        outr[v * TPB + t] = o;
    }
}

extern "C" void kernel_launch(void* const* d_in, const int* in_sizes, int n_in,
                              void* d_out, int out_size) {
    const float* x = (const float*)d_in[0];
    float* out = (float*)d_out;
    int rows = in_sizes[0] / NCOL;
    topk_mask_kernel<<<rows, TPB>>>(x, out);
}

// round 6
// speedup vs baseline: 1.3911x; 1.3911x over previous
#include <cuda_runtime.h>
#include <stdint.h>

#define NCOL   4096
#define TPB    256
#define KSEL   64
#define TGUESS 1.7f        // prefilter guess; exact fallback if it fails
#define CAP    2048        // candidate capacity (expected ~183 per row)

// float -> order-preserving uint32 (larger float => larger unsigned key)
__device__ __forceinline__ uint32_t f2k(float f) {
    uint32_t u = __float_as_uint(f);
    return u ^ (uint32_t)((((int32_t)u) >> 31) | (int32_t)0x80000000);
}
__device__ __forceinline__ float k2f(uint32_t k) {
    uint32_t u = (k & 0x80000000u) ? (k ^ 0x80000000u) : ~k;
    return __uint_as_float(u);
}

// inclusive block scan over TPB=256 uint32 values. wsum: shared[8].
__device__ __forceinline__ uint32_t block_scan_inc(uint32_t val, uint32_t* wsum, int t) {
    __syncthreads();
    int lane = t & 31, w = t >> 5;
#pragma unroll
    for (int off = 1; off < 32; off <<= 1) {
        uint32_t n = __shfl_up_sync(0xffffffffu, val, off);
        if (lane >= off) val += n;
    }
    if (lane == 31) wsum[w] = val;
    __syncthreads();
    if (w == 0) {
        uint32_t s = (lane < 8) ? wsum[lane] : 0u;
#pragma unroll
        for (int off = 1; off < 8; off <<= 1) {
            uint32_t n = __shfl_up_sync(0xffffffffu, s, off);
            if (lane >= off) s += n;
        }
        if (lane < 8) wsum[lane] = s;
    }
    __syncthreads();
    uint32_t base = (w > 0) ? wsum[w - 1] : 0u;
    return val + base;
}

__global__ __launch_bounds__(TPB, 8) void topk_mask_kernel(const float* __restrict__ x,
                                                           float* __restrict__ out) {
    __shared__ uint32_t cand[CAP];            // candidate keys
    __shared__ uint16_t candcol[CAP];         // candidate columns
    __shared__ uint32_t hist[256];
    __shared__ uint32_t wsum[8];
    __shared__ uint32_t s_pos, s_bin, s_above, s_h;
    __shared__ uint32_t keep_bm[NCOL / 32];   // fallback tie path only

    const int t    = threadIdx.x;
    const int lane = t & 31;
    const size_t row_off = (size_t)blockIdx.x * NCOL;
    const float4* __restrict__ xr = (const float4*)(x + row_off);
    float4* __restrict__ outr     = (float4*)(out + row_off);

    if (t == 0) s_pos = 0;
    __syncthreads();

    // ---- phase 1: fused load + provisional masked store + candidate gather ----
    // On the fast path Tf > TGUESS, so elements <= TGUESS are final zeros already.
#pragma unroll
    for (int v = 0; v < 4; v++) {
        float4 q = xr[v * TPB + t];
        float4 o;
        o.x = (q.x > TGUESS) ? q.x : 0.0f;
        o.y = (q.y > TGUESS) ? q.y : 0.0f;
        o.z = (q.z > TGUESS) ? q.z : 0.0f;
        o.w = (q.w > TGUESS) ? q.w : 0.0f;
        outr[v * TPB + t] = o;
        const float* qp = (const float*)&q;
#pragma unroll
        for (int j = 0; j < 4; j++) {
            float fv = qp[j];
            if (fv > TGUESS) {
                uint32_t p = atomicAdd(&s_pos, 1u);
                if (p < CAP) {
                    cand[p]    = f2k(fv);
                    candcol[p] = (uint16_t)((v * TPB + t) * 4 + j);
                }
            }
        }
    }
    __syncthreads();
    const uint32_t C = s_pos;
    const bool fast = (C >= KSEL && C <= CAP);

    uint32_t prefix = 0, mmask = 0, kth = KSEL, total_eq = 0;

    if (fast) {
        // ---- phase 2: exact 4x8-bit radix select over candidates (block-wide) ----
#pragma unroll
        for (int pass = 0; pass < 4; pass++) {
            const int shift = 24 - 8 * pass;
            hist[t] = 0;
            __syncthreads();
            for (uint32_t i = t; i < C; i += TPB) {
                uint32_t kk = cand[i];
                if ((kk & mmask) == prefix)
                    atomicAdd(&hist[(kk >> shift) & 0xFFu], 1u);
            }
            __syncthreads();
            uint32_t hh = hist[255 - t];
            uint32_t S = block_scan_inc(hh, wsum, t);
            if (S >= kth && (S - hh) < kth) {        // unique boundary thread
                s_bin = (uint32_t)(255 - t); s_above = S - hh; s_h = hh;
            }
            __syncthreads();
            prefix |= (s_bin << shift);
            mmask  |= (0xFFu << shift);
            kth    -= s_above;
            total_eq = s_h;                           // valid after last pass
            __syncthreads();
        }
        const uint32_t keyT = prefix;
        const uint32_t need = kth;
        const bool tie_rank = (total_eq > need);      // rare

        // ---- phase 3: sparse fix-up — zero candidates below Tf (and excess ties) ----
        for (uint32_t i = t; i < C; i += TPB) {
            uint32_t kk = cand[i];
            if (kk < keyT) {
                out[row_off + candcol[i]] = 0.0f;
            } else if (kk == keyT && tie_rank) {
                uint32_t col = candcol[i], r = 0;
                for (uint32_t j = 0; j < C; j++)
                    r += (cand[j] == keyT && candcol[j] < col) ? 1u : 0u;
                if (r >= need) out[row_off + col] = 0.0f;
            }
        }
        return;
    }

    // ================= fallback: exact full-row select + full rewrite =================
#pragma unroll 1
    for (int pass = 0; pass < 4; pass++) {
        const int shift = 24 - 8 * pass;
        hist[t] = 0;
        __syncthreads();
        for (int i = t; i < NCOL; i += TPB) {
            uint32_t kk = f2k(x[row_off + i]);
            if ((kk & mmask) == prefix) {
                uint32_t bin = (kk >> shift) & 0xFFu;
                unsigned act = __activemask();
                unsigned grp = __match_any_sync(act, bin);
                if ((grp & ((1u << lane) - 1u)) == 0u)
                    atomicAdd(&hist[bin], (uint32_t)__popc(grp));
            }
        }
        __syncthreads();
        uint32_t hh = hist[255 - t];
        uint32_t S = block_scan_inc(hh, wsum, t);
        if (S >= kth && (S - hh) < kth) {
            s_bin = (uint32_t)(255 - t); s_above = S - hh; s_h = hh;
        }
        __syncthreads();
        prefix |= (s_bin << shift);
        mmask  |= (0xFFu << shift);
        kth    -= s_above;
        total_eq = s_h;
        __syncthreads();
    }
    const uint32_t need = kth;
    const float Tf = k2f(prefix);
    const bool tie_rank = (total_eq > need);

    if (tie_rank) {
        uint16_t* tiebuf = (uint16_t*)cand;
        if (t == 0) s_pos = 0;
        for (int i = t; i < NCOL / 32; i += TPB) keep_bm[i] = 0;
        __syncthreads();
        for (int i = t; i < NCOL; i += TPB) {
            if (x[row_off + i] == Tf) {
                uint32_t p = atomicAdd(&s_pos, 1u);
                tiebuf[p] = (uint16_t)i;
            }
        }
        __syncthreads();
        uint32_t total = s_pos;
        for (uint32_t i = t; i < total; i += TPB) {
            uint32_t ci = tiebuf[i], r = 0;
            for (uint32_t j = 0; j < total; j++) r += (tiebuf[j] < ci) ? 1u : 0u;
            if (r < need) atomicOr(&keep_bm[ci >> 5], 1u << (ci & 31));
        }
        __syncthreads();
#pragma unroll
        for (int v = 0; v < 4; v++) {
            float4 q = xr[v * TPB + t];
            float4 o;
            float* ip = (float*)&q;
            float* op = (float*)&o;
#pragma unroll
            for (int j = 0; j < 4; j++) {
                float fv = ip[j];
                float val = 0.0f;
                if (fv > Tf) val = fv;
                else if (fv == Tf) {
                    uint32_t col = (uint32_t)(v * TPB + t) * 4u + (uint32_t)j;
                    if ((keep_bm[col >> 5] >> (col & 31)) & 1u) val = fv;
                }
                op[j] = val;
            }
            outr[v * TPB + t] = o;
        }
    } else {
#pragma unroll
        for (int v = 0; v < 4; v++) {
            float4 q = xr[v * TPB + t];
            float4 o;
            o.x = (q.x >= Tf) ? q.x : 0.0f;
            o.y = (q.y >= Tf) ? q.y : 0.0f;
            o.z = (q.z >= Tf) ? q.z : 0.0f;
            o.w = (q.w >= Tf) ? q.w : 0.0f;
            outr[v * TPB + t] = o;
        }
    }
}

extern "C" void kernel_launch(void* const* d_in, const int* in_sizes, int n_in,
                              void* d_out, int out_size) {
    const float* x = (const float*)d_in[0];
    float* out = (float*)d_out;
    int rows = in_sizes[0] / NCOL;
    topk_mask_kernel<<<rows, TPB>>>(x, out);
}

// round 7
// speedup vs baseline: 1.4834x; 1.0664x over previous
#include <cuda_runtime.h>
#include <stdint.h>

#define NCOL     4096
#define TPB      256
#define KSEL     64
#define TGUESS   1.7f      // prefilter guess; exact fallback if it fails
#define CAP      2048      // candidate capacity (expected ~183 per row)
#define SMALLCAP 64        // early-exit bound for boundary-bin brute force

// float -> order-preserving uint32 (fallback path; fast path uses raw bits of positives)
__device__ __forceinline__ uint32_t f2k(float f) {
    uint32_t u = __float_as_uint(f);
    return u ^ (uint32_t)((((int32_t)u) >> 31) | (int32_t)0x80000000);
}
__device__ __forceinline__ float k2f(uint32_t k) {
    uint32_t u = (k & 0x80000000u) ? (k ^ 0x80000000u) : ~k;
    return __uint_as_float(u);
}

// inclusive block scan over TPB=256 uint32 values (fallback only). wsum: shared[8].
__device__ __forceinline__ uint32_t block_scan_inc(uint32_t val, uint32_t* wsum, int t) {
    __syncthreads();
    int lane = t & 31, w = t >> 5;
#pragma unroll
    for (int off = 1; off < 32; off <<= 1) {
        uint32_t n = __shfl_up_sync(0xffffffffu, val, off);
        if (lane >= off) val += n;
    }
    if (lane == 31) wsum[w] = val;
    __syncthreads();
    if (w == 0) {
        uint32_t s = (lane < 8) ? wsum[lane] : 0u;
#pragma unroll
        for (int off = 1; off < 8; off <<= 1) {
            uint32_t n = __shfl_up_sync(0xffffffffu, s, off);
            if (lane >= off) s += n;
        }
        if (lane < 8) wsum[lane] = s;
    }
    __syncthreads();
    uint32_t base = (w > 0) ? wsum[w - 1] : 0u;
    return val + base;
}

__global__ __launch_bounds__(TPB, 8) void topk_mask_kernel(const float* __restrict__ x,
                                                           float* __restrict__ out) {
    __shared__ uint32_t cand[CAP];            // candidate raw-bit keys (all positive)
    __shared__ uint16_t candcol[CAP];         // candidate columns
    __shared__ uint32_t hist[256];            // also reused as the small gather buffer
    __shared__ uint32_t wsum[8];
    __shared__ uint32_t s_pos, s_bin, s_above, s_h;
    __shared__ uint32_t s_cnt2, s_keyT, s_gt, s_eqc;
    __shared__ uint32_t keep_bm[NCOL / 32];   // fallback tie path only

    const int t    = threadIdx.x;
    const int lane = t & 31;
    const size_t row_off = (size_t)blockIdx.x * NCOL;
    const float4* __restrict__ xr = (const float4*)(x + row_off);
    float4* __restrict__ outr     = (float4*)(out + row_off);

    if (t == 0) s_pos = 0;
    __syncthreads();

    // ---- phase 1: fused load + provisional masked store + candidate gather ----
    // On the fast path Tf > TGUESS, so elements <= TGUESS are final zeros already.
#pragma unroll
    for (int v = 0; v < 4; v++) {
        float4 q = xr[v * TPB + t];
        float4 o;
        o.x = (q.x > TGUESS) ? q.x : 0.0f;
        o.y = (q.y > TGUESS) ? q.y : 0.0f;
        o.z = (q.z > TGUESS) ? q.z : 0.0f;
        o.w = (q.w > TGUESS) ? q.w : 0.0f;
        outr[v * TPB + t] = o;
        const float* qp = (const float*)&q;
#pragma unroll
        for (int j = 0; j < 4; j++) {
            float fv = qp[j];
            if (fv > TGUESS) {
                uint32_t p = atomicAdd(&s_pos, 1u);
                if (p < CAP) {
                    cand[p]    = __float_as_uint(fv);   // positive: raw bits are ordered
                    candcol[p] = (uint16_t)((v * TPB + t) * 4 + j);
                }
            }
        }
    }
    __syncthreads();
    const uint32_t C = s_pos;
    const bool fast = (C >= KSEL && C <= CAP);

    if (fast) {
        // ---- phase 2: radix passes with warp-0 scan + small-set early exit ----
        uint32_t prefix = 0, mmask = 0, kth = KSEL;
        uint32_t keyT, need, total_eq;
        bool small = false;
        int pass = 0;
#pragma unroll 1
        for (; pass < 4; pass++) {
            const int shift = 24 - 8 * pass;
            hist[t] = 0;
            __syncthreads();
            for (uint32_t i = t; i < C; i += TPB) {
                uint32_t kk = cand[i];
                if ((kk & mmask) == prefix)
                    atomicAdd(&hist[(kk >> shift) & 0xFFu], 1u);
            }
            __syncthreads();
            if (t < 32) {       // warp-0 suffix scan over 256 bins, 8 descending bins/lane
                uint32_t run = 0;
#pragma unroll
                for (int j = 0; j < 8; j++) run += hist[255 - t * 8 - j];
                uint32_t excl = run;
#pragma unroll
                for (int off = 1; off < 32; off <<= 1) {
                    uint32_t n = __shfl_up_sync(0xffffffffu, excl, off);
                    if (t >= off) excl += n;
                }
                excl -= run;
                uint32_t S = excl;
#pragma unroll
                for (int j = 0; j < 8; j++) {
                    uint32_t bin = 255u - (uint32_t)(t * 8 + j);
                    uint32_t hh = hist[bin];
                    S += hh;
                    if (S >= kth && (S - hh) < kth) {   // unique boundary bin
                        s_bin = bin; s_above = S - hh; s_h = hh;
                    }
                }
            }
            __syncthreads();
            prefix |= (s_bin << shift);
            mmask  |= (0xFFu << shift);
            kth    -= s_above;
            total_eq = s_h;
            small = (pass < 3) && (s_h <= SMALLCAP);
            __syncthreads();    // protects hist/s_* WAR for next pass or small gather
            if (small) break;
        }

        if (small) {
            // gather the <=64 candidates matching the prefix, brute-force on warp 0
            if (t == 0) s_cnt2 = 0;
            __syncthreads();
            for (uint32_t i = t; i < C; i += TPB) {
                uint32_t kk = cand[i];
                if ((kk & mmask) == prefix) {
                    uint32_t p = atomicAdd(&s_cnt2, 1u);
                    hist[p] = kk;                       // reuse hist as small buffer
                }
            }
            __syncthreads();
            if (t < 32) {
                uint32_t n = s_cnt2;                    // == s_h
                for (uint32_t i = t; i < n; i += 32) {
                    uint32_t e = hist[i];
                    uint32_t gt = 0, eq = 0;
                    for (uint32_t j = 0; j < n; j++) {
                        uint32_t g = hist[j];
                        gt += (g > e) ? 1u : 0u;
                        eq += (g == e) ? 1u : 0u;
                    }
                    if (gt < kth && gt + eq >= kth) {   // e is the exact k-th largest
                        s_keyT = e; s_gt = gt; s_eqc = eq;
                    }
                }
            }
            __syncthreads();
            keyT = s_keyT; need = kth - s_gt; total_eq = s_eqc;
        } else {
            keyT = prefix; need = kth;                  // exact after 4 full passes
        }
        const bool tie_rank = (total_eq > need);        // rare

        // ---- phase 3: sparse fix-up — zero candidates below T (and excess ties) ----
        for (uint32_t i = t; i < C; i += TPB) {
            uint32_t kk = cand[i];
            if (kk < keyT) {
                out[row_off + candcol[i]] = 0.0f;
            } else if (kk == keyT && tie_rank) {
                uint32_t col = candcol[i], r = 0;
                for (uint32_t j = 0; j < C; j++)
                    r += (cand[j] == keyT && candcol[j] < col) ? 1u : 0u;
                if (r >= need) out[row_off + col] = 0.0f;
            }
        }
        return;
    }

    // ================= fallback: exact full-row select + full rewrite =================
    uint32_t prefix = 0, mmask = 0, kth = KSEL, total_eq = 0;
#pragma unroll 1
    for (int pass = 0; pass < 4; pass++) {
        const int shift = 24 - 8 * pass;
        hist[t] = 0;
        __syncthreads();
        for (int i = t; i < NCOL; i += TPB) {
            uint32_t kk = f2k(x[row_off + i]);
            if ((kk & mmask) == prefix) {
                uint32_t bin = (kk >> shift) & 0xFFu;
                unsigned act = __activemask();
                unsigned grp = __match_any_sync(act, bin);
                if ((grp & ((1u << lane) - 1u)) == 0u)
                    atomicAdd(&hist[bin], (uint32_t)__popc(grp));
            }
        }
        __syncthreads();
        uint32_t hh = hist[255 - t];
        uint32_t S = block_scan_inc(hh, wsum, t);
        if (S >= kth && (S - hh) < kth) {
            s_bin = (uint32_t)(255 - t); s_above = S - hh; s_h = hh;
        }
        __syncthreads();
        prefix |= (s_bin << shift);
        mmask  |= (0xFFu << shift);
        kth    -= s_above;
        total_eq = s_h;
        __syncthreads();
    }
    const uint32_t need = kth;
    const float Tf = k2f(prefix);
    const bool tie_rank = (total_eq > need);

    if (tie_rank) {
        uint16_t* tiebuf = (uint16_t*)cand;
        if (t == 0) s_pos = 0;
        for (int i = t; i < NCOL / 32; i += TPB) keep_bm[i] = 0;
        __syncthreads();
        for (int i = t; i < NCOL; i += TPB) {
            if (x[row_off + i] == Tf) {
                uint32_t p = atomicAdd(&s_pos, 1u);
                tiebuf[p] = (uint16_t)i;
            }
        }
        __syncthreads();
        uint32_t total = s_pos;
        for (uint32_t i = t; i < total; i += TPB) {
            uint32_t ci = tiebuf[i], r = 0;
            for (uint32_t j = 0; j < total; j++) r += (tiebuf[j] < ci) ? 1u : 0u;
            if (r < need) atomicOr(&keep_bm[ci >> 5], 1u << (ci & 31));
        }
        __syncthreads();
#pragma unroll
        for (int v = 0; v < 4; v++) {
            float4 q = xr[v * TPB + t];
            float4 o;
            float* ip = (float*)&q;
            float* op = (float*)&o;
#pragma unroll
            for (int j = 0; j < 4; j++) {
                float fv = ip[j];
                float val = 0.0f;
                if (fv > Tf) val = fv;
                else if (fv == Tf) {
                    uint32_t col = (uint32_t)(v * TPB + t) * 4u + (uint32_t)j;
                    if ((keep_bm[col >> 5] >> (col & 31)) & 1u) val = fv;
                }
                op[j] = val;
            }
            outr[v * TPB + t] = o;
        }
    } else {
#pragma unroll
        for (int v = 0; v < 4; v++) {
            float4 q = xr[v * TPB + t];
            float4 o;
            o.x = (q.x >= Tf) ? q.x : 0.0f;
            o.y = (q.y >= Tf) ? q.y : 0.0f;
            o.z = (q.z >= Tf) ? q.z : 0.0f;
            o.w = (q.w >= Tf) ? q.w : 0.0f;
            outr[v * TPB + t] = o;
        }
    }
}

extern "C" void kernel_launch(void* const* d_in, const int* in_sizes, int n_in,
                              void* d_out, int out_size) {
    const float* x = (const float*)d_in[0];
    float* out = (float*)d_out;
    int rows = in_sizes[0] / NCOL;
    topk_mask_kernel<<<rows, TPB>>>(x, out);
}

// round 8
// speedup vs baseline: 1.6297x; 1.0986x over previous
#include <cuda_runtime.h>
#include <stdint.h>

#define NCOL     4096
#define TPB      256
#define KSEL     64
#define TGUESS   1.7f      // prefilter guess; exact fallback if it fails
#define BSCALE   512.0f    // bucket scale: bin = min(1023, (int)((fv-TGUESS)*BSCALE))
#define NBIN     1024
#define CAP      2048      // candidate capacity (expected ~183 per row)
#define SMALLCAP 64        // boundary-bin brute-force bound

// float -> order-preserving uint32 (fallback path only)
__device__ __forceinline__ uint32_t f2k(float f) {
    uint32_t u = __float_as_uint(f);
    return u ^ (uint32_t)((((int32_t)u) >> 31) | (int32_t)0x80000000);
}
__device__ __forceinline__ float k2f(uint32_t k) {
    uint32_t u = (k & 0x80000000u) ? (k ^ 0x80000000u) : ~k;
    return __uint_as_float(u);
}

// inclusive block scan over TPB=256 uint32 values (fallback only). wsum: shared[8].
__device__ __forceinline__ uint32_t block_scan_inc(uint32_t val, uint32_t* wsum, int t) {
    __syncthreads();
    int lane = t & 31, w = t >> 5;
#pragma unroll
    for (int off = 1; off < 32; off <<= 1) {
        uint32_t n = __shfl_up_sync(0xffffffffu, val, off);
        if (lane >= off) val += n;
    }
    if (lane == 31) wsum[w] = val;
    __syncthreads();
    if (w == 0) {
        uint32_t s = (lane < 8) ? wsum[lane] : 0u;
#pragma unroll
        for (int off = 1; off < 8; off <<= 1) {
            uint32_t n = __shfl_up_sync(0xffffffffu, s, off);
            if (lane >= off) s += n;
        }
        if (lane < 8) wsum[lane] = s;
    }
    __syncthreads();
    uint32_t base = (w > 0) ? wsum[w - 1] : 0u;
    return val + base;
}

__device__ __forceinline__ int bucket_of(float fv) {
    int b = (int)((fv - TGUESS) * BSCALE);
    return (b > NBIN - 1) ? (NBIN - 1) : b;     // fv > TGUESS ensures b >= 0
}

__global__ __launch_bounds__(TPB, 8) void topk_mask_kernel(const float* __restrict__ x,
                                                           float* __restrict__ out) {
    __shared__ uint32_t cand[CAP];            // candidate raw-bit keys (all positive)
    __shared__ uint16_t candcol[CAP];         // candidate columns
    __shared__ uint32_t hist[NBIN];           // bucket histogram
    __shared__ uint32_t psum[256];            // 4-bin partial sums; reused as brute buffer
    __shared__ uint32_t wsum[8];
    __shared__ uint32_t s_pos, s_bin, s_above, s_h;
    __shared__ uint32_t s_cnt2, s_keyT, s_gt, s_eqc;
    __shared__ uint32_t keep_bm[NCOL / 32];   // fallback tie path only

    const int t    = threadIdx.x;
    const int lane = t & 31;
    const size_t row_off = (size_t)blockIdx.x * NCOL;
    const float4* __restrict__ xr = (const float4*)(x + row_off);
    float4* __restrict__ outr     = (float4*)(out + row_off);

    if (t == 0) { s_pos = 0; s_cnt2 = 0; }
    ((uint4*)hist)[t] = make_uint4(0, 0, 0, 0);   // zero 1024 bins, 16B per thread
    __syncthreads();

    // ---- phase 1: fused load + provisional masked store + candidate gather ----
    // On the fast path Tf > TGUESS, so elements <= TGUESS are final zeros already.
#pragma unroll
    for (int v = 0; v < 4; v++) {
        float4 q = xr[v * TPB + t];
        float4 o;
        o.x = (q.x > TGUESS) ? q.x : 0.0f;
        o.y = (q.y > TGUESS) ? q.y : 0.0f;
        o.z = (q.z > TGUESS) ? q.z : 0.0f;
        o.w = (q.w > TGUESS) ? q.w : 0.0f;
        outr[v * TPB + t] = o;
        const float* qp = (const float*)&q;
#pragma unroll
        for (int j = 0; j < 4; j++) {
            float fv = qp[j];
            if (fv > TGUESS) {
                uint32_t p = atomicAdd(&s_pos, 1u);
                if (p < CAP) {
                    cand[p]    = __float_as_uint(fv);   // positive: raw bits ordered
                    candcol[p] = (uint16_t)((v * TPB + t) * 4 + j);
                }
            }
        }
    }
    __syncthreads();
    const uint32_t C = s_pos;
    const bool fast = (C >= KSEL && C <= CAP);
    bool bucket_ok = false;

    if (fast) {
        // ---- phase 2a: single bucket histogram over candidates ----
        for (uint32_t i = t; i < C; i += TPB)
            atomicAdd(&hist[bucket_of(__uint_as_float(cand[i]))], 1u);
        __syncthreads();

        // ---- phase 2b: hierarchical conflict-free suffix search for boundary bin ----
        {
            uint4 h4 = ((const uint4*)hist)[t];            // bins 4t..4t+3
            psum[t] = h4.x + h4.y + h4.z + h4.w;
        }
        __syncthreads();
        if (t < 32) {
            const int sb = 31 - t;                         // lane t owns superbin sb (desc)
            uint4 a = ((const uint4*)psum)[2 * sb];
            uint4 b = ((const uint4*)psum)[2 * sb + 1];
            uint32_t s8 = a.x + a.y + a.z + a.w + b.x + b.y + b.z + b.w;
            uint32_t S = s8;                               // suffix over superbins > sb
#pragma unroll
            for (int off = 1; off < 32; off <<= 1) {
                uint32_t n = __shfl_up_sync(0xffffffffu, S, off);
                if (t >= off) S += n;
            }
            if (S >= KSEL && (S - s8) < KSEL) {            // boundary superbin: this lane
                uint32_t run = S - s8;                     // count in bins above superbin
                for (int g = 7; g >= 0; g--) {             // psum groups, descending
                    uint32_t pv = psum[8 * sb + g];
                    if (run + pv >= KSEL) {
                        for (int bb = 4 * (8 * sb + g) + 3;; bb--) {
                            uint32_t hv = hist[bb];
                            if (run + hv >= KSEL) { s_bin = (uint32_t)bb; s_above = run; s_h = hv; break; }
                            run += hv;
                        }
                        break;
                    }
                    run += pv;
                }
            }
        }
        __syncthreads();
        bucket_ok = (s_h <= SMALLCAP);

        if (bucket_ok) {
            const uint32_t kth2 = KSEL - s_above;          // rank within boundary bin
            // gather boundary-bin candidates (typically 1-3)
            const int target = (int)s_bin;
            for (uint32_t i = t; i < C; i += TPB) {
                uint32_t kk = cand[i];
                if (bucket_of(__uint_as_float(kk)) == target) {
                    uint32_t p = atomicAdd(&s_cnt2, 1u);
                    psum[p] = kk;                          // reuse psum as brute buffer
                }
            }
            __syncthreads();
            if (t < 32) {
                uint32_t n = s_cnt2;                       // == s_h
                for (uint32_t i = (uint32_t)t; i < n; i += 32) {
                    uint32_t e = psum[i];
                    uint32_t gt = 0, eq = 0;
                    for (uint32_t j = 0; j < n; j++) {
                        uint32_t g = psum[j];
                        gt += (g > e) ? 1u : 0u;
                        eq += (g == e) ? 1u : 0u;
                    }
                    if (gt < kth2 && gt + eq >= kth2) {    // exact k-th within bin
                        s_keyT = e; s_gt = gt; s_eqc = eq;
                    }
                }
            }
            __syncthreads();
            const uint32_t keyT = s_keyT;
            const uint32_t need = kth2 - s_gt;
            const bool tie_rank = (s_eqc > need);          // rare

            // ---- phase 3: sparse fix-up — zero candidates below T (and excess ties) ----
            for (uint32_t i = t; i < C; i += TPB) {
                uint32_t kk = cand[i];
                if (kk < keyT) {
                    out[row_off + candcol[i]] = 0.0f;
                } else if (kk == keyT && tie_rank) {
                    uint32_t col = candcol[i], r = 0;
                    for (uint32_t j = 0; j < C; j++)
                        r += (cand[j] == keyT && candcol[j] < col) ? 1u : 0u;
                    if (r >= need) out[row_off + col] = 0.0f;
                }
            }
            return;
        }
        __syncthreads();   // bucket failed: fall through to exact full-row path
    }

    // ================= fallback: exact full-row select + full rewrite =================
    uint32_t prefix = 0, mmask = 0, kth = KSEL, total_eq = 0;
#pragma unroll 1
    for (int pass = 0; pass < 4; pass++) {
        const int shift = 24 - 8 * pass;
        hist[t] = 0;
        __syncthreads();
        for (int i = t; i < NCOL; i += TPB) {
            uint32_t kk = f2k(x[row_off + i]);
            if ((kk & mmask) == prefix) {
                uint32_t bin = (kk >> shift) & 0xFFu;
                unsigned act = __activemask();
                unsigned grp = __match_any_sync(act, bin);
                if ((grp & ((1u << lane) - 1u)) == 0u)
                    atomicAdd(&hist[bin], (uint32_t)__popc(grp));
            }
        }
        __syncthreads();
        uint32_t hh = hist[255 - t];
        uint32_t S = block_scan_inc(hh, wsum, t);
        if (S >= kth && (S - hh) < kth) {
            s_bin = (uint32_t)(255 - t); s_above = S - hh; s_h = hh;
        }
        __syncthreads();
        prefix |= (s_bin << shift);
        mmask  |= (0xFFu << shift);
        kth    -= s_above;
        total_eq = s_h;
        __syncthreads();
    }
    const uint32_t need = kth;
    const float Tf = k2f(prefix);
    const bool tie_rank = (total_eq > need);

    if (tie_rank) {
        uint16_t* tiebuf = (uint16_t*)cand;
        if (t == 0) s_pos = 0;
        for (int i = t; i < NCOL / 32; i += TPB) keep_bm[i] = 0;
        __syncthreads();
        for (int i = t; i < NCOL; i += TPB) {
            if (x[row_off + i] == Tf) {
                uint32_t p = atomicAdd(&s_pos, 1u);
                tiebuf[p] = (uint16_t)i;
            }
        }
        __syncthreads();
        uint32_t total = s_pos;
        for (uint32_t i = t; i < total; i += TPB) {
            uint32_t ci = tiebuf[i], r = 0;
            for (uint32_t j = 0; j < total; j++) r += (tiebuf[j] < ci) ? 1u : 0u;
            if (r < need) atomicOr(&keep_bm[ci >> 5], 1u << (ci & 31));
        }
        __syncthreads();
#pragma unroll
        for (int v = 0; v < 4; v++) {
            float4 q = xr[v * TPB + t];
            float4 o;
            float* ip = (float*)&q;
            float* op = (float*)&o;
#pragma unroll
            for (int j = 0; j < 4; j++) {
                float fv = ip[j];
                float val = 0.0f;
                if (fv > Tf) val = fv;
                else if (fv == Tf) {
                    uint32_t col = (uint32_t)(v * TPB + t) * 4u + (uint32_t)j;
                    if ((keep_bm[col >> 5] >> (col & 31)) & 1u) val = fv;
                }
                op[j] = val;
            }
            outr[v * TPB + t] = o;
        }
    } else {
#pragma unroll
        for (int v = 0; v < 4; v++) {
            float4 q = xr[v * TPB + t];
            float4 o;
            o.x = (q.x >= Tf) ? q.x : 0.0f;
            o.y = (q.y >= Tf) ? q.y : 0.0f;
            o.z = (q.z >= Tf) ? q.z : 0.0f;
            o.w = (q.w >= Tf) ? q.w : 0.0f;
            outr[v * TPB + t] = o;
        }
    }
}

extern "C" void kernel_launch(void* const* d_in, const int* in_sizes, int n_in,
                              void* d_out, int out_size) {
    const float* x = (const float*)d_in[0];
    float* out = (float*)d_out;
    int rows = in_sizes[0] / NCOL;
    topk_mask_kernel<<<rows, TPB>>>(x, out);
}

// round 9
// speedup vs baseline: 1.6638x; 1.0209x over previous
#include <cuda_runtime.h>
#include <stdint.h>

#define NCOL     4096
#define TPB      256
#define KSEL     64
#define TGUESS   1.7f      // prefilter guess; exact fallback if it fails
#define BSCALE   512.0f    // bucket scale: bin = min(1023, (int)((fv-TGUESS)*BSCALE))
#define NBIN     1024
#define CAP      2048      // candidate capacity (expected ~183 per row)
#define SMALLCAP 64        // boundary-bin brute-force bound

// float -> order-preserving uint32 (fallback path only)
__device__ __forceinline__ uint32_t f2k(float f) {
    uint32_t u = __float_as_uint(f);
    return u ^ (uint32_t)((((int32_t)u) >> 31) | (int32_t)0x80000000);
}
__device__ __forceinline__ float k2f(uint32_t k) {
    uint32_t u = (k & 0x80000000u) ? (k ^ 0x80000000u) : ~k;
    return __uint_as_float(u);
}

// inclusive block scan over TPB=256 uint32 values (fallback only). wsum: shared[8].
__device__ __forceinline__ uint32_t block_scan_inc(uint32_t val, uint32_t* wsum, int t) {
    __syncthreads();
    int lane = t & 31, w = t >> 5;
#pragma unroll
    for (int off = 1; off < 32; off <<= 1) {
        uint32_t n = __shfl_up_sync(0xffffffffu, val, off);
        if (lane >= off) val += n;
    }
    if (lane == 31) wsum[w] = val;
    __syncthreads();
    if (w == 0) {
        uint32_t s = (lane < 8) ? wsum[lane] : 0u;
#pragma unroll
        for (int off = 1; off < 8; off <<= 1) {
            uint32_t n = __shfl_up_sync(0xffffffffu, s, off);
            if (lane >= off) s += n;
        }
        if (lane < 8) wsum[lane] = s;
    }
    __syncthreads();
    uint32_t base = (w > 0) ? wsum[w - 1] : 0u;
    return val + base;
}

__device__ __forceinline__ int bucket_of(float fv) {
    int b = (int)((fv - TGUESS) * BSCALE);
    return (b > NBIN - 1) ? (NBIN - 1) : b;     // fv > TGUESS ensures b >= 0
}

__global__ __launch_bounds__(TPB, 8) void topk_mask_kernel(const float* __restrict__ x,
                                                           float* __restrict__ out) {
    // packed candidate: (key_bits << 12) | (4095 - col). Strict total order ==
    // "larger value first, then lower column" — exactly top_k tie semantics.
    __shared__ uint64_t cand64[CAP];          // 16 KB
    __shared__ uint32_t hist[NBIN];           // bucket histogram (fallback uses first 256)
    __shared__ uint32_t psum[256];            // 4-bin partial sums
    __shared__ uint64_t brute[SMALLCAP];      // boundary-bin gather buffer
    __shared__ uint32_t wsum[8];
    __shared__ uint32_t s_pos, s_bin, s_above, s_h, s_cnt2;
    __shared__ uint64_t s_keyT64;
    __shared__ uint32_t keep_bm[NCOL / 32];   // fallback tie path only

    const int t    = threadIdx.x;
    const int lane = t & 31;
    const size_t row_off = (size_t)blockIdx.x * NCOL;
    const float4* __restrict__ xr = (const float4*)(x + row_off);
    float4* __restrict__ outr     = (float4*)(out + row_off);

    if (t == 0) { s_pos = 0; s_cnt2 = 0; s_h = 0xFFFFFFFFu; }
    ((uint4*)hist)[t] = make_uint4(0, 0, 0, 0);   // zero 1024 bins
    __syncthreads();

    // ---- phase 1: batched loads (MLP=4) + provisional masked store +
    //      fused candidate gather + bucket histogram ----
    float4 q0 = xr[0 * TPB + t];
    float4 q1 = xr[1 * TPB + t];
    float4 q2 = xr[2 * TPB + t];
    float4 q3 = xr[3 * TPB + t];

#define DO_V(qv, v)                                                          \
    {                                                                        \
        float4 o;                                                            \
        o.x = (qv.x > TGUESS) ? qv.x : 0.0f;                                 \
        o.y = (qv.y > TGUESS) ? qv.y : 0.0f;                                 \
        o.z = (qv.z > TGUESS) ? qv.z : 0.0f;                                 \
        o.w = (qv.w > TGUESS) ? qv.w : 0.0f;                                 \
        outr[(v) * TPB + t] = o;                                             \
        const float* qp = (const float*)&qv;                                 \
        _Pragma("unroll")                                                    \
        for (int j = 0; j < 4; j++) {                                        \
            float fv = qp[j];                                                \
            if (fv > TGUESS) {                                               \
                uint32_t p = atomicAdd(&s_pos, 1u);                          \
                if (p < CAP) {                                               \
                    uint32_t col = (uint32_t)(((v) * TPB + t) * 4 + j);      \
                    cand64[p] = ((uint64_t)__float_as_uint(fv) << 12)        \
                                | (uint64_t)(4095u - col);                   \
                    atomicAdd(&hist[bucket_of(fv)], 1u);                     \
                }                                                            \
            }                                                                \
        }                                                                    \
    }
    DO_V(q0, 0)
    DO_V(q1, 1)
    DO_V(q2, 2)
    DO_V(q3, 3)
#undef DO_V

    __syncthreads();
    const uint32_t C = s_pos;
    const bool fast = (C >= KSEL && C <= CAP);

    if (fast) {
        // ---- phase 2: hierarchical conflict-free suffix search for boundary bin ----
        {
            uint4 h4 = ((const uint4*)hist)[t];            // bins 4t..4t+3
            psum[t] = h4.x + h4.y + h4.z + h4.w;
        }
        __syncthreads();
        if (t < 32) {
            const int sb = 31 - t;                         // lane t owns superbin sb (desc)
            uint4 a = ((const uint4*)psum)[2 * sb];
            uint4 b = ((const uint4*)psum)[2 * sb + 1];
            uint32_t s8 = a.x + a.y + a.z + a.w + b.x + b.y + b.z + b.w;
            uint32_t S = s8;
#pragma unroll
            for (int off = 1; off < 32; off <<= 1) {
                uint32_t n = __shfl_up_sync(0xffffffffu, S, off);
                if (t >= off) S += n;
            }
            if (S >= KSEL && (S - s8) < KSEL) {            // boundary superbin: this lane
                uint32_t run = S - s8;
                for (int g = 7; g >= 0; g--) {
                    uint32_t pv = psum[8 * sb + g];
                    if (run + pv >= KSEL) {
                        for (int bb = 4 * (8 * sb + g) + 3;; bb--) {
                            uint32_t hv = hist[bb];
                            if (run + hv >= KSEL) { s_bin = (uint32_t)bb; s_above = run; s_h = hv; break; }
                            run += hv;
                        }
                        break;
                    }
                    run += pv;
                }
            }
        }
        __syncthreads();

        if (s_h <= SMALLCAP) {
            const uint32_t kth2 = KSEL - s_above;          // rank within boundary bin
            const int target = (int)s_bin;
            for (uint32_t i = t; i < C; i += TPB) {
                uint64_t p = cand64[i];
                if (bucket_of(__uint_as_float((uint32_t)(p >> 12))) == target) {
                    uint32_t q = atomicAdd(&s_cnt2, 1u);
                    brute[q] = p;
                }
            }
            __syncthreads();
            if (t < 32) {                                  // all packed values distinct
                uint32_t n = s_cnt2;                       // == s_h
                for (uint32_t i = (uint32_t)t; i < n; i += 32) {
                    uint64_t e = brute[i];
                    uint32_t gt = 0;
                    for (uint32_t j = 0; j < n; j++) gt += (brute[j] > e) ? 1u : 0u;
                    if (gt == kth2 - 1) s_keyT64 = e;      // exact k-th within bin
                }
            }
            __syncthreads();
            const uint64_t keyT64 = s_keyT64;

            // ---- phase 3: sparse fix-up — zero candidates strictly below threshold ----
            for (uint32_t i = t; i < C; i += TPB) {
                uint64_t p = cand64[i];
                if (p < keyT64)
                    out[row_off + (4095u - (uint32_t)(p & 0xFFFu))] = 0.0f;
            }
            return;
        }
        __syncthreads();   // degenerate bin: fall through to exact full-row path
    }

    // ================= fallback: exact full-row select + full rewrite =================
    uint32_t prefix = 0, mmask = 0, kth = KSEL, total_eq = 0;
#pragma unroll 1
    for (int pass = 0; pass < 4; pass++) {
        const int shift = 24 - 8 * pass;
        hist[t] = 0;
        __syncthreads();
        for (int i = t; i < NCOL; i += TPB) {
            uint32_t kk = f2k(x[row_off + i]);
            if ((kk & mmask) == prefix) {
                uint32_t bin = (kk >> shift) & 0xFFu;
                unsigned act = __activemask();
                unsigned grp = __match_any_sync(act, bin);
                if ((grp & ((1u << lane) - 1u)) == 0u)
                    atomicAdd(&hist[bin], (uint32_t)__popc(grp));
            }
        }
        __syncthreads();
        uint32_t hh = hist[255 - t];
        uint32_t S = block_scan_inc(hh, wsum, t);
        if (S >= kth && (S - hh) < kth) {
            s_bin = (uint32_t)(255 - t); s_above = S - hh; s_h = hh;
        }
        __syncthreads();
        prefix |= (s_bin << shift);
        mmask  |= (0xFFu << shift);
        kth    -= s_above;
        total_eq = s_h;
        __syncthreads();
    }
    const uint32_t need = kth;
    const float Tf = k2f(prefix);
    const bool tie_rank = (total_eq > need);

    if (tie_rank) {
        uint16_t* tiebuf = (uint16_t*)cand64;
        if (t == 0) s_pos = 0;
        for (int i = t; i < NCOL / 32; i += TPB) keep_bm[i] = 0;
        __syncthreads();
        for (int i = t; i < NCOL; i += TPB) {
            if (x[row_off + i] == Tf) {
                uint32_t p = atomicAdd(&s_pos, 1u);
                tiebuf[p] = (uint16_t)i;
            }
        }
        __syncthreads();
        uint32_t total = s_pos;
        for (uint32_t i = t; i < total; i += TPB) {
            uint32_t ci = tiebuf[i], r = 0;
            for (uint32_t j = 0; j < total; j++) r += (tiebuf[j] < ci) ? 1u : 0u;
            if (r < need) atomicOr(&keep_bm[ci >> 5], 1u << (ci & 31));
        }
        __syncthreads();
#pragma unroll
        for (int v = 0; v < 4; v++) {
            float4 q = xr[v * TPB + t];
            float4 o;
            float* ip = (float*)&q;
            float* op = (float*)&o;
#pragma unroll
            for (int j = 0; j < 4; j++) {
                float fv = ip[j];
                float val = 0.0f;
                if (fv > Tf) val = fv;
                else if (fv == Tf) {
                    uint32_t col = (uint32_t)(v * TPB + t) * 4u + (uint32_t)j;
                    if ((keep_bm[col >> 5] >> (col & 31)) & 1u) val = fv;
                }
                op[j] = val;
            }
            outr[v * TPB + t] = o;
        }
    } else {
#pragma unroll
        for (int v = 0; v < 4; v++) {
            float4 q = xr[v * TPB + t];
            float4 o;
            o.x = (q.x >= Tf) ? q.x : 0.0f;
            o.y = (q.y >= Tf) ? q.y : 0.0f;
            o.z = (q.z >= Tf) ? q.z : 0.0f;
            o.w = (q.w >= Tf) ? q.w : 0.0f;
            outr[v * TPB + t] = o;
        }
    }
}

extern "C" void kernel_launch(void* const* d_in, const int* in_sizes, int n_in,
                              void* d_out, int out_size) {
    const float* x = (const float*)d_in[0];
    float* out = (float*)d_out;
    int rows = in_sizes[0] / NCOL;
    topk_mask_kernel<<<rows, TPB>>>(x, out);
}

// round 10
// speedup vs baseline: 1.7335x; 1.0419x over previous
#include <cuda_runtime.h>
#include <stdint.h>

#define NCOL     4096
#define TPB      256
#define KSEL     64
#define TGUESS   1.9f      // prefilter guess; exact fallback if it fails
#define BSCALE   512.0f    // bucket scale: bin = min(1023, (int)((fv-TGUESS)*BSCALE))
#define NBIN     1024
#define CAP      2048      // candidate capacity (expected ~118 per row)
#define SMALLCAP 64        // boundary-bin brute-force bound

// float -> order-preserving uint32 (fallback path only)
__device__ __forceinline__ uint32_t f2k(float f) {
    uint32_t u = __float_as_uint(f);
    return u ^ (uint32_t)((((int32_t)u) >> 31) | (int32_t)0x80000000);
}
__device__ __forceinline__ float k2f(uint32_t k) {
    uint32_t u = (k & 0x80000000u) ? (k ^ 0x80000000u) : ~k;
    return __uint_as_float(u);
}

// inclusive block scan over TPB=256 uint32 values (fallback only). wsum: shared[8].
__device__ __forceinline__ uint32_t block_scan_inc(uint32_t val, uint32_t* wsum, int t) {
    __syncthreads();
    int lane = t & 31, w = t >> 5;
#pragma unroll
    for (int off = 1; off < 32; off <<= 1) {
        uint32_t n = __shfl_up_sync(0xffffffffu, val, off);
        if (lane >= off) val += n;
    }
    if (lane == 31) wsum[w] = val;
    __syncthreads();
    if (w == 0) {
        uint32_t s = (lane < 8) ? wsum[lane] : 0u;
#pragma unroll
        for (int off = 1; off < 8; off <<= 1) {
            uint32_t n = __shfl_up_sync(0xffffffffu, s, off);
            if (lane >= off) s += n;
        }
        if (lane < 8) wsum[lane] = s;
    }
    __syncthreads();
    uint32_t base = (w > 0) ? wsum[w - 1] : 0u;
    return val + base;
}

__device__ __forceinline__ int bucket_of(float fv) {
    int b = (int)((fv - TGUESS) * BSCALE);
    return (b > NBIN - 1) ? (NBIN - 1) : b;     // fv > TGUESS ensures b >= 0
}

__device__ __forceinline__ uint64_t pack_cand(float fv, uint32_t col) {
    // strict total order == "larger value first, then lower column"
    return ((uint64_t)__float_as_uint(fv) << 12) | (uint64_t)(4095u - col);
}

__global__ __launch_bounds__(TPB, 8) void topk_mask_kernel(const float* __restrict__ x,
                                                           float* __restrict__ out) {
    __shared__ uint64_t cand64[CAP];          // 16 KB packed candidates
    __shared__ uint32_t hist[NBIN];           // bucket histogram (fallback uses first 256)
    __shared__ uint32_t psum[256];            // 4-bin partial sums
    __shared__ uint64_t brute[SMALLCAP];      // boundary-bin gather buffer
    __shared__ uint32_t wsum[8];
    __shared__ uint32_t s_pos, s_bin, s_above, s_h, s_cnt2;
    __shared__ uint64_t s_keyT64;
    __shared__ uint32_t keep_bm[NCOL / 32];   // fallback tie path only

    const int t    = threadIdx.x;
    const int lane = t & 31;
    const size_t row_off = (size_t)blockIdx.x * NCOL;
    const float4* __restrict__ xr = (const float4*)(x + row_off);
    float4* __restrict__ outr     = (float4*)(out + row_off);

    if (t == 0) { s_pos = 0; s_cnt2 = 0; s_h = 0xFFFFFFFFu; }
    ((uint4*)hist)[t] = make_uint4(0, 0, 0, 0);   // zero 1024 bins
    __syncthreads();

    // ---- phase 1: batched loads (MLP=4) + provisional masked store +
    //      warp-compacted candidate gather (one atomic per float4 group) ----
    float4 qq[4];
#pragma unroll
    for (int v = 0; v < 4; v++) qq[v] = xr[v * TPB + t];

#pragma unroll
    for (int v = 0; v < 4; v++) {
        float4 qv = qq[v];
        bool p0 = (qv.x > TGUESS), p1 = (qv.y > TGUESS);
        bool p2 = (qv.z > TGUESS), p3 = (qv.w > TGUESS);
        float4 o;
        o.x = p0 ? qv.x : 0.0f;
        o.y = p1 ? qv.y : 0.0f;
        o.z = p2 ? qv.z : 0.0f;
        o.w = p3 ? qv.w : 0.0f;
        outr[v * TPB + t] = o;

        unsigned b0 = __ballot_sync(0xffffffffu, p0);
        unsigned b1 = __ballot_sync(0xffffffffu, p1);
        unsigned b2 = __ballot_sync(0xffffffffu, p2);
        unsigned b3 = __ballot_sync(0xffffffffu, p3);
        uint32_t c0 = (uint32_t)__popc(b0), c1 = (uint32_t)__popc(b1);
        uint32_t c2 = (uint32_t)__popc(b2), c3 = (uint32_t)__popc(b3);
        uint32_t tot = c0 + c1 + c2 + c3;
        if (tot) {
            uint32_t base = 0;
            if (lane == 0) base = atomicAdd(&s_pos, tot);
            base = __shfl_sync(0xffffffffu, base, 0);
            unsigned lm = (1u << lane) - 1u;
            uint32_t colb = (uint32_t)(v * TPB + t) * 4u;
            uint32_t i0 = base + (uint32_t)__popc(b0 & lm);
            uint32_t i1 = base + c0 + (uint32_t)__popc(b1 & lm);
            uint32_t i2 = base + c0 + c1 + (uint32_t)__popc(b2 & lm);
            uint32_t i3 = base + c0 + c1 + c2 + (uint32_t)__popc(b3 & lm);
            if (p0 && i0 < CAP) cand64[i0] = pack_cand(qv.x, colb + 0u);
            if (p1 && i1 < CAP) cand64[i1] = pack_cand(qv.y, colb + 1u);
            if (p2 && i2 < CAP) cand64[i2] = pack_cand(qv.z, colb + 2u);
            if (p3 && i3 < CAP) cand64[i3] = pack_cand(qv.w, colb + 3u);
        }
    }
    __syncthreads();
    const uint32_t C = s_pos;
    const bool fast = (C >= KSEL && C <= CAP);

    if (fast) {
        // ---- phase 2a: bucket histogram over compacted candidates (C ~ 118) ----
        for (uint32_t i = t; i < C; i += TPB)
            atomicAdd(&hist[bucket_of(__uint_as_float((uint32_t)(cand64[i] >> 12)))], 1u);
        __syncthreads();

        // ---- phase 2b: hierarchical conflict-free suffix search for boundary bin ----
        {
            uint4 h4 = ((const uint4*)hist)[t];            // bins 4t..4t+3
            psum[t] = h4.x + h4.y + h4.z + h4.w;
        }
        __syncthreads();
        if (t < 32) {
            const int sb = 31 - t;                         // lane t owns superbin sb (desc)
            uint4 a = ((const uint4*)psum)[2 * sb];
            uint4 b = ((const uint4*)psum)[2 * sb + 1];
            uint32_t s8 = a.x + a.y + a.z + a.w + b.x + b.y + b.z + b.w;
            uint32_t S = s8;
#pragma unroll
            for (int off = 1; off < 32; off <<= 1) {
                uint32_t n = __shfl_up_sync(0xffffffffu, S, off);
                if (t >= off) S += n;
            }
            if (S >= KSEL && (S - s8) < KSEL) {            // boundary superbin: this lane
                uint32_t run = S - s8;
                for (int g = 7; g >= 0; g--) {
                    uint32_t pv = psum[8 * sb + g];
                    if (run + pv >= KSEL) {
                        for (int bb = 4 * (8 * sb + g) + 3;; bb--) {
                            uint32_t hv = hist[bb];
                            if (run + hv >= KSEL) { s_bin = (uint32_t)bb; s_above = run; s_h = hv; break; }
                            run += hv;
                        }
                        break;
                    }
                    run += pv;
                }
            }
        }
        __syncthreads();

        if (s_h <= SMALLCAP) {
            const uint32_t kth2 = KSEL - s_above;          // rank within boundary bin
            const int target = (int)s_bin;
            for (uint32_t i = t; i < C; i += TPB) {
                uint64_t p = cand64[i];
                if (bucket_of(__uint_as_float((uint32_t)(p >> 12))) == target) {
                    uint32_t q = atomicAdd(&s_cnt2, 1u);
                    brute[q] = p;
                }
            }
            __syncthreads();
            if (t < 32) {                                  // all packed values distinct
                uint32_t n = s_cnt2;                       // == s_h
                for (uint32_t i = (uint32_t)t; i < n; i += 32) {
                    uint64_t e = brute[i];
                    uint32_t gt = 0;
                    for (uint32_t j = 0; j < n; j++) gt += (brute[j] > e) ? 1u : 0u;
                    if (gt == kth2 - 1) s_keyT64 = e;      // exact k-th within bin
                }
            }
            __syncthreads();
            const uint64_t keyT64 = s_keyT64;

            // ---- phase 3: sparse fix-up — zero candidates strictly below threshold ----
            for (uint32_t i = t; i < C; i += TPB) {
                uint64_t p = cand64[i];
                if (p < keyT64)
                    out[row_off + (4095u - (uint32_t)(p & 0xFFFu))] = 0.0f;
            }
            return;
        }
        __syncthreads();   // degenerate bin: fall through to exact full-row path
    }

    // ================= fallback: exact full-row select + full rewrite =================
    uint32_t prefix = 0, mmask = 0, kth = KSEL, total_eq = 0;
#pragma unroll 1
    for (int pass = 0; pass < 4; pass++) {
        const int shift = 24 - 8 * pass;
        hist[t] = 0;
        __syncthreads();
        for (int i = t; i < NCOL; i += TPB) {
            uint32_t kk = f2k(x[row_off + i]);
            if ((kk & mmask) == prefix) {
                uint32_t bin = (kk >> shift) & 0xFFu;
                unsigned act = __activemask();
                unsigned grp = __match_any_sync(act, bin);
                if ((grp & ((1u << lane) - 1u)) == 0u)
                    atomicAdd(&hist[bin], (uint32_t)__popc(grp));
            }
        }
        __syncthreads();
        uint32_t hh = hist[255 - t];
        uint32_t S = block_scan_inc(hh, wsum, t);
        if (S >= kth && (S - hh) < kth) {
            s_bin = (uint32_t)(255 - t); s_above = S - hh; s_h = hh;
        }
        __syncthreads();
        prefix |= (s_bin << shift);
        mmask  |= (0xFFu << shift);
        kth    -= s_above;
        total_eq = s_h;
        __syncthreads();
    }
    const uint32_t need = kth;
    const float Tf = k2f(prefix);
    const bool tie_rank = (total_eq > need);

    if (tie_rank) {
        uint16_t* tiebuf = (uint16_t*)cand64;
        if (t == 0) s_pos = 0;
        for (int i = t; i < NCOL / 32; i += TPB) keep_bm[i] = 0;
        __syncthreads();
        for (int i = t; i < NCOL; i += TPB) {
            if (x[row_off + i] == Tf) {
                uint32_t p = atomicAdd(&s_pos, 1u);
                tiebuf[p] = (uint16_t)i;
            }
        }
        __syncthreads();
        uint32_t total = s_pos;
        for (uint32_t i = t; i < total; i += TPB) {
            uint32_t ci = tiebuf[i], r = 0;
            for (uint32_t j = 0; j < total; j++) r += (tiebuf[j] < ci) ? 1u : 0u;
            if (r < need) atomicOr(&keep_bm[ci >> 5], 1u << (ci & 31));
        }
        __syncthreads();
#pragma unroll
        for (int v = 0; v < 4; v++) {
            float4 q = xr[v * TPB + t];
            float4 o;
            float* ip = (float*)&q;
            float* op = (float*)&o;
#pragma unroll
            for (int j = 0; j < 4; j++) {
                float fv = ip[j];
                float val = 0.0f;
                if (fv > Tf) val = fv;
                else if (fv == Tf) {
                    uint32_t col = (uint32_t)(v * TPB + t) * 4u + (uint32_t)j;
                    if ((keep_bm[col >> 5] >> (col & 31)) & 1u) val = fv;
                }
                op[j] = val;
            }
            outr[v * TPB + t] = o;
        }
    } else {
#pragma unroll
        for (int v = 0; v < 4; v++) {
            float4 q = xr[v * TPB + t];
            float4 o;
            o.x = (q.x >= Tf) ? q.x : 0.0f;
            o.y = (q.y >= Tf) ? q.y : 0.0f;
            o.z = (q.z >= Tf) ? q.z : 0.0f;
            o.w = (q.w >= Tf) ? q.w : 0.0f;
            outr[v * TPB + t] = o;
        }
    }
}

extern "C" void kernel_launch(void* const* d_in, const int* in_sizes, int n_in,
                              void* d_out, int out_size) {
    const float* x = (const float*)d_in[0];
    float* out = (float*)d_out;
    int rows = in_sizes[0] / NCOL;
    topk_mask_kernel<<<rows, TPB>>>(x, out);
}

// round 11
// speedup vs baseline: 1.7684x; 1.0201x over previous
#include <cuda_runtime.h>
#include <stdint.h>

#define NCOL     4096
#define TPB      256
#define KSEL     64
#define TGUESS   1.9f      // prefilter guess; exact fallback if it fails
#define BSCALE   512.0f    // bucket scale: bin = min(1023, (int)((fv-TGUESS)*BSCALE))
#define NBIN     1024
#define CAP      2048      // candidate capacity (expected ~118 per row)
#define SMALLCAP 64        // boundary-bin brute-force bound
#define NWORD    128       // 4096 elements / 32 bits

// float -> order-preserving uint32 (fallback path only)
__device__ __forceinline__ uint32_t f2k(float f) {
    uint32_t u = __float_as_uint(f);
    return u ^ (uint32_t)((((int32_t)u) >> 31) | (int32_t)0x80000000);
}
__device__ __forceinline__ float k2f(uint32_t k) {
    uint32_t u = (k & 0x80000000u) ? (k ^ 0x80000000u) : ~k;
    return __uint_as_float(u);
}

// inclusive block scan over TPB=256 uint32 values (fallback only). wsum: shared[8].
__device__ __forceinline__ uint32_t block_scan_inc(uint32_t val, uint32_t* wsum, int t) {
    __syncthreads();
    int lane = t & 31, w = t >> 5;
#pragma unroll
    for (int off = 1; off < 32; off <<= 1) {
        uint32_t n = __shfl_up_sync(0xffffffffu, val, off);
        if (lane >= off) val += n;
    }
    if (lane == 31) wsum[w] = val;
    __syncthreads();
    if (w == 0) {
        uint32_t s = (lane < 8) ? wsum[lane] : 0u;
#pragma unroll
        for (int off = 1; off < 8; off <<= 1) {
            uint32_t n = __shfl_up_sync(0xffffffffu, s, off);
            if (lane >= off) s += n;
        }
        if (lane < 8) wsum[lane] = s;
    }
    __syncthreads();
    uint32_t base = (w > 0) ? wsum[w - 1] : 0u;
    return val + base;
}

__device__ __forceinline__ int bucket_of(float fv) {
    int b = (int)((fv - TGUESS) * BSCALE);
    return (b > NBIN - 1) ? (NBIN - 1) : b;     // fv > TGUESS ensures b >= 0
}

__device__ __forceinline__ uint64_t pack_cand(float fv, uint32_t col) {
    // strict total order == "larger value first, then lower column" (top_k tie rule)
    return ((uint64_t)__float_as_uint(fv) << 12) | (uint64_t)(4095u - col);
}

__global__ __launch_bounds__(TPB, 8) void topk_mask_kernel(const float* __restrict__ x,
                                                           float* __restrict__ out) {
    __shared__ uint64_t cand64[CAP];          // 16 KB packed candidates
    __shared__ uint32_t hist[NBIN];           // bucket histogram (fallback uses first 256)
    __shared__ uint32_t psum[256];            // 4-bin partial sums
    __shared__ uint32_t bitmap[NWORD];        // candidate presence ballots
    __shared__ uint64_t brute[SMALLCAP];      // boundary-bin gather buffer
    __shared__ uint32_t wsum[8];
    __shared__ uint32_t s_pos, s_bin, s_above, s_h, s_cnt2;
    __shared__ uint64_t s_keyT64;
    __shared__ uint32_t keep_bm[NCOL / 32];   // fallback tie path only

    const int t    = threadIdx.x;
    const int lane = t & 31;
    const int w    = t >> 5;
    const size_t row_off = (size_t)blockIdx.x * NCOL;
    const float4* __restrict__ xr = (const float4*)(x + row_off);
    float4* __restrict__ outr     = (float4*)(out + row_off);

    if (t == 0) { s_pos = 0; s_cnt2 = 0; s_h = 0xFFFFFFFFu; }
    ((uint4*)hist)[t] = make_uint4(0, 0, 0, 0);   // zero 1024 bins
    __syncthreads();

    // ---- phase 1: batched loads (MLP=4) + provisional masked store +
    //      candidate presence recorded as ballot words only (no per-element stores) ----
    float4 qq[4];
#pragma unroll
    for (int v = 0; v < 4; v++) qq[v] = xr[v * TPB + t];

#pragma unroll
    for (int v = 0; v < 4; v++) {
        float4 qv = qq[v];
        bool p0 = (qv.x > TGUESS), p1 = (qv.y > TGUESS);
        bool p2 = (qv.z > TGUESS), p3 = (qv.w > TGUESS);
        float4 o;
        o.x = p0 ? qv.x : 0.0f;
        o.y = p1 ? qv.y : 0.0f;
        o.z = p2 ? qv.z : 0.0f;
        o.w = p3 ? qv.w : 0.0f;
        outr[v * TPB + t] = o;
        unsigned b0 = __ballot_sync(0xffffffffu, p0);
        unsigned b1 = __ballot_sync(0xffffffffu, p1);
        unsigned b2 = __ballot_sync(0xffffffffu, p2);
        unsigned b3 = __ballot_sync(0xffffffffu, p3);
        if (lane == 0)
            ((uint4*)bitmap)[v * 8 + w] = make_uint4(b0, b1, b2, b3);
    }
    __syncthreads();

    // ---- phase 2a: reconstruct + compact candidates from bitmap (threads 0-127) ----
    // word i: v = i>>5, w = (i>>2)&7, j = i&3; bit l -> col = (v*256 + w*32 + l)*4 + j
    if (t < NWORD) {
        uint32_t m = bitmap[t];
        if (m) {
            const uint32_t vv = (uint32_t)(t >> 5);
            const uint32_t ww = (uint32_t)((t >> 2) & 7);
            const uint32_t jj = (uint32_t)(t & 3);
            uint32_t n = (uint32_t)__popc(m);
            uint32_t base = atomicAdd(&s_pos, n);
            while (m) {
                int l = __ffs(m) - 1;
                m &= m - 1;
                uint32_t col = (vv * 256u + ww * 32u + (uint32_t)l) * 4u + jj;
                float fv = x[row_off + col];          // L2-resident (just read)
                if (base < CAP) cand64[base] = pack_cand(fv, col);
                base++;
                atomicAdd(&hist[bucket_of(fv)], 1u);
            }
        }
    }
    __syncthreads();
    const uint32_t C = s_pos;
    const bool fast = (C >= KSEL && C <= CAP);

    if (fast) {
        // ---- phase 2b: hierarchical conflict-free suffix search for boundary bin ----
        {
            uint4 h4 = ((const uint4*)hist)[t];            // bins 4t..4t+3
            psum[t] = h4.x + h4.y + h4.z + h4.w;
        }
        __syncthreads();
        if (t < 32) {
            const int sb = 31 - t;                         // lane t owns superbin sb (desc)
            uint4 a = ((const uint4*)psum)[2 * sb];
            uint4 b = ((const uint4*)psum)[2 * sb + 1];
            uint32_t s8 = a.x + a.y + a.z + a.w + b.x + b.y + b.z + b.w;
            uint32_t S = s8;
#pragma unroll
            for (int off = 1; off < 32; off <<= 1) {
                uint32_t n = __shfl_up_sync(0xffffffffu, S, off);
                if (t >= off) S += n;
            }
            if (S >= KSEL && (S - s8) < KSEL) {            // boundary superbin: this lane
                uint32_t run = S - s8;
                for (int g = 7; g >= 0; g--) {
                    uint32_t pv = psum[8 * sb + g];
                    if (run + pv >= KSEL) {
                        for (int bb = 4 * (8 * sb + g) + 3;; bb--) {
                            uint32_t hv = hist[bb];
                            if (run + hv >= KSEL) { s_bin = (uint32_t)bb; s_above = run; s_h = hv; break; }
                            run += hv;
                        }
                        break;
                    }
                    run += pv;
                }
            }
        }
        __syncthreads();

        if (s_h <= SMALLCAP) {
            const uint32_t kth2 = KSEL - s_above;          // rank within boundary bin
            const int target = (int)s_bin;
            for (uint32_t i = t; i < C; i += TPB) {
                uint64_t p = cand64[i];
                if (bucket_of(__uint_as_float((uint32_t)(p >> 12))) == target) {
                    uint32_t q = atomicAdd(&s_cnt2, 1u);
                    brute[q] = p;
                }
            }
            __syncthreads();
            if (t < 32) {                                  // all packed values distinct
                uint32_t n = s_cnt2;                       // == s_h
                for (uint32_t i = (uint32_t)t; i < n; i += 32) {
                    uint64_t e = brute[i];
                    uint32_t gt = 0;
                    for (uint32_t j = 0; j < n; j++) gt += (brute[j] > e) ? 1u : 0u;
                    if (gt == kth2 - 1) s_keyT64 = e;      // exact k-th overall
                }
            }
            __syncthreads();
            const uint64_t keyT64 = s_keyT64;

            // ---- phase 3: sparse fix-up — zero candidates strictly below threshold ----
            for (uint32_t i = t; i < C; i += TPB) {
                uint64_t p = cand64[i];
                if (p < keyT64)
                    out[row_off + (4095u - (uint32_t)(p & 0xFFFu))] = 0.0f;
            }
            return;
        }
        __syncthreads();   // degenerate bin: fall through to exact full-row path
    }

    // ================= fallback: exact full-row select + full rewrite =================
    uint32_t prefix = 0, mmask = 0, kth = KSEL, total_eq = 0;
#pragma unroll 1
    for (int pass = 0; pass < 4; pass++) {
        const int shift = 24 - 8 * pass;
        hist[t] = 0;
        __syncthreads();
        for (int i = t; i < NCOL; i += TPB) {
            uint32_t kk = f2k(x[row_off + i]);
            if ((kk & mmask) == prefix) {
                uint32_t bin = (kk >> shift) & 0xFFu;
                unsigned act = __activemask();
                unsigned grp = __match_any_sync(act, bin);
                if ((grp & ((1u << lane) - 1u)) == 0u)
                    atomicAdd(&hist[bin], (uint32_t)__popc(grp));
            }
        }
        __syncthreads();
        uint32_t hh = hist[255 - t];
        uint32_t S = block_scan_inc(hh, wsum, t);
        if (S >= kth && (S - hh) < kth) {
            s_bin = (uint32_t)(255 - t); s_above = S - hh; s_h = hh;
        }
        __syncthreads();
        prefix |= (s_bin << shift);
        mmask  |= (0xFFu << shift);
        kth    -= s_above;
        total_eq = s_h;
        __syncthreads();
    }
    const uint32_t need = kth;
    const float Tf = k2f(prefix);
    const bool tie_rank = (total_eq > need);

    if (tie_rank) {
        uint16_t* tiebuf = (uint16_t*)cand64;
        if (t == 0) s_pos = 0;
        for (int i = t; i < NCOL / 32; i += TPB) keep_bm[i] = 0;
        __syncthreads();
        for (int i = t; i < NCOL; i += TPB) {
            if (x[row_off + i] == Tf) {
                uint32_t p = atomicAdd(&s_pos, 1u);
                tiebuf[p] = (uint16_t)i;
            }
        }
        __syncthreads();
        uint32_t total = s_pos;
        for (uint32_t i = t; i < total; i += TPB) {
            uint32_t ci = tiebuf[i], r = 0;
            for (uint32_t j = 0; j < total; j++) r += (tiebuf[j] < ci) ? 1u : 0u;
            if (r < need) atomicOr(&keep_bm[ci >> 5], 1u << (ci & 31));
        }
        __syncthreads();
#pragma unroll
        for (int v = 0; v < 4; v++) {
            float4 q = xr[v * TPB + t];
            float4 o;
            float* ip = (float*)&q;
            float* op = (float*)&o;
#pragma unroll
            for (int j = 0; j < 4; j++) {
                float fv = ip[j];
                float val = 0.0f;
                if (fv > Tf) val = fv;
                else if (fv == Tf) {
                    uint32_t col = (uint32_t)(v * TPB + t) * 4u + (uint32_t)j;
                    if ((keep_bm[col >> 5] >> (col & 31)) & 1u) val = fv;
                }
                op[j] = val;
            }
            outr[v * TPB + t] = o;
        }
    } else {
#pragma unroll
        for (int v = 0; v < 4; v++) {
            float4 q = xr[v * TPB + t];
            float4 o;
            o.x = (q.x >= Tf) ? q.x : 0.0f;
            o.y = (q.y >= Tf) ? q.y : 0.0f;
            o.z = (q.z >= Tf) ? q.z : 0.0f;
            o.w = (q.w >= Tf) ? q.w : 0.0f;
            outr[v * TPB + t] = o;
        }
    }
}

extern "C" void kernel_launch(void* const* d_in, const int* in_sizes, int n_in,
                              void* d_out, int out_size) {
    const float* x = (const float*)d_in[0];
    float* out = (float*)d_out;
    int rows = in_sizes[0] / NCOL;
    topk_mask_kernel<<<rows, TPB>>>(x, out);
}